// round 7
// baseline (speedup 1.0000x reference)
#include <cuda_runtime.h>
#include <math_constants.h>

#define NT 32
#define NQ 256
#define NNODE 8192
#define DD 128
#define CHN 32
#define KK 16
#define NBF 8
#define BB 4
#define CAP 4096      // hard correctness cap (R6-proven)
#define NREG 2048     // elements kept in regs/smem-coords fast path
#define NTG 8
#define TPT 4

__device__ float g_nfext[NNODE * DD];
__device__ float g_tf[DD];
__device__ int   g_range[BB + 1];
__device__ float g_coef[6 * CHN];
__device__ float g_partial[NT * NQ * 6];

static __device__ __forceinline__ unsigned long long umin64(unsigned long long a, unsigned long long b) {
    return a < b ? a : b;
}

static __device__ __forceinline__ float3 qrot(float w, float x, float y, float z, float3 v) {
    float uvx = y * v.z - z * v.y;
    float uvy = z * v.x - x * v.z;
    float uvz = x * v.y - y * v.x;
    float wx = y * uvz - z * uvy;
    float wy = z * uvx - x * uvz;
    float wz = x * uvy - y * uvx;
    float3 r;
    r.x = v.x + 2.f * (w * uvx + wx);
    r.y = v.y + 2.f * (w * uvy + wy);
    r.z = v.z + 2.f * (w * uvz + wz);
    return r;
}

// ---- precompute: nf_ext (register-tiled GEMM, bit-identical chains) + misc ---
__global__ __launch_bounds__(128) void k_pre(
    const float* __restrict__ nf, const float* __restrict__ Wext,
    const float* __restrict__ te, const float* __restrict__ Wtime,
    const int* __restrict__ nbatch,
    const float* __restrict__ wp_lin, const float* __restrict__ Wv_lin,
    const float* __restrict__ wp_ang, const float* __restrict__ Wv_ang) {
    int tid = threadIdx.x;
    if (blockIdx.x == NNODE / 16) {
        {
            float acc = 0.f;
            for (int k = 0; k < DD; k++) acc = fmaf(te[k], Wtime[k * DD + tid], acc);
            g_tf[tid] = 1.f + acc;
        }
        if (tid <= BB) {
            int lo = 0, hi = NNODE;
            if (tid == BB) lo = NNODE;
            else {
                while (lo < hi) { int m = (lo + hi) >> 1; if (nbatch[m] < tid) lo = m + 1; else hi = m; }
            }
            g_range[tid] = lo;
        }
        if (tid < CHN) {
            for (int g = 0; g < 6; g++) {
                const float* wp = (g < 3) ? wp_lin : wp_ang;
                const float* Wv = (g < 3) ? Wv_lin : Wv_ang;
                int gg = g % 3;
                int wrow = gg * CHN + tid;
                float s = 0.f;
                for (int o = 0; o < CHN; o++) s += Wv[wrow * CHN + o];
                g_coef[g * CHN + tid] = wp[(2 + gg) * CHN + tid] * s * (1.f / (float)CHN);
            }
        }
        return;
    }
    __shared__ float snf[16 * 132];            // padded rows: bank-safe
    int b = blockIdx.x;
    for (int idx = tid; idx < 16 * DD; idx += 128) {
        int r = idx >> 7, c = idx & 127;
        snf[r * 132 + c] = nf[(b * 16 + r) * DD + c];
    }
    __syncthreads();
    int ng = tid >> 5;                          // warp id = node group (broadcast LDS)
    int cg = tid & 31;                          // 4 cols per thread
    float acc[4][4];
#pragma unroll
    for (int i = 0; i < 4; i++)
#pragma unroll
        for (int j = 0; j < 4; j++) acc[i][j] = 0.f;
    for (int k = 0; k < DD; k++) {
        float4 wv = *(const float4*)&Wext[k * DD + cg * 4];
        float a0 = snf[(ng * 4 + 0) * 132 + k];
        float a1 = snf[(ng * 4 + 1) * 132 + k];
        float a2 = snf[(ng * 4 + 2) * 132 + k];
        float a3 = snf[(ng * 4 + 3) * 132 + k];
        acc[0][0] = fmaf(a0, wv.x, acc[0][0]); acc[0][1] = fmaf(a0, wv.y, acc[0][1]);
        acc[0][2] = fmaf(a0, wv.z, acc[0][2]); acc[0][3] = fmaf(a0, wv.w, acc[0][3]);
        acc[1][0] = fmaf(a1, wv.x, acc[1][0]); acc[1][1] = fmaf(a1, wv.y, acc[1][1]);
        acc[1][2] = fmaf(a1, wv.z, acc[1][2]); acc[1][3] = fmaf(a1, wv.w, acc[1][3]);
        acc[2][0] = fmaf(a2, wv.x, acc[2][0]); acc[2][1] = fmaf(a2, wv.y, acc[2][1]);
        acc[2][2] = fmaf(a2, wv.z, acc[2][2]); acc[2][3] = fmaf(a2, wv.w, acc[2][3]);
        acc[3][0] = fmaf(a3, wv.x, acc[3][0]); acc[3][1] = fmaf(a3, wv.y, acc[3][1]);
        acc[3][2] = fmaf(a3, wv.z, acc[3][2]); acc[3][3] = fmaf(a3, wv.w, acc[3][3]);
    }
#pragma unroll
    for (int i = 0; i < 4; i++) {
        float4 o = { acc[i][0], acc[i][1], acc[i][2], acc[i][3] };
        *(float4*)&g_nfext[(b * 16 + ng * 4 + i) * DD + cg * 4] = o;
    }
}

// ---- main: block = (query, 4 transforms); warp-local selection + merge -------
__global__ __launch_bounds__(256) void k_main(
    const float* __restrict__ T, const float* __restrict__ qwgt,
    const float* __restrict__ qf, const float* __restrict__ qcrd,
    const float* __restrict__ ncoord, const float* __restrict__ Wrbf,
    const int* __restrict__ qbatch) {
    __shared__ float sx[NREG], sy[NREG], sz[NREG];   // coord cache, i < 2048
    __shared__ float sdov[CAP - NREG];               // d2 overflow, i >= 2048
    __shared__ unsigned long long scand[8 * KK];
    __shared__ float srbf[KK * NBF];
    __shared__ float sfield[DD];
    __shared__ int ssel[KK];
    __shared__ float sd2sel[KK];

    int qi = blockIdx.x, tg = blockIdx.y, tid = threadIdx.x;
    int lane = tid & 31, wid = tid >> 5;

    int b = qbatch[qi];
    int lo = g_range[b];
    int n = g_range[b + 1] - lo;
    if (n > CAP) n = CAP;
    int ncache = n < NREG ? n : NREG;
    float3 qc0 = { qcrd[qi * 3 + 0], qcrd[qi * 3 + 1], qcrd[qi * 3 + 2] };

    for (int i = tid; i < ncache; i += 256) {
        sx[i] = ncoord[(lo + i) * 3 + 0];
        sy[i] = ncoord[(lo + i) * 3 + 1];
        sz[i] = ncoord[(lo + i) * 3 + 2];
    }

    float e_s = 0.f, e_vx = 0.f, e_vy = 0.f, e_vz = 0.f;
    float e_al = 0.f, e_bl = 0.f, e_el = 0.f, e_aa = 0.f, e_ba = 0.f, e_ea = 0.f, e_w = 0.f;
    if (tid < CHN) {
        e_s  = qf[qi * DD + tid];
        e_vx = qf[qi * DD + CHN + 3 * tid + 0];
        e_vy = qf[qi * DD + CHN + 3 * tid + 1];
        e_vz = qf[qi * DD + CHN + 3 * tid + 2];
        e_al = g_coef[tid];           e_bl = g_coef[CHN + tid];     e_el = g_coef[2 * CHN + tid];
        e_aa = g_coef[3 * CHN + tid]; e_ba = g_coef[4 * CHN + tid]; e_ea = g_coef[5 * CHN + tid];
        e_w  = qwgt[qi];
    }
    __syncthreads();

    for (int tt = 0; tt < TPT; tt++) {
        int t = tg * TPT + tt;
        float qw0 = T[t * 7 + 0], qx = T[t * 7 + 1], qy = T[t * 7 + 2], qz = T[t * 7 + 3];
        float3 p = qrot(qw0, qx, qy, qz, qc0);
        p.x += T[t * 7 + 4]; p.y += T[t * 7 + 5]; p.z += T[t * 7 + 6];

        // distances: j<8 in regs (i<2048 via smem coords), j>=8 into sdov
        float d2v[8];
        unsigned long long tm = ~0ull;
#pragma unroll
        for (int j = 0; j < 8; j++) {
            int i = tid + 256 * j;
            float d2 = CUDART_INF_F;
            if (i < ncache) {
                float dx = p.x - sx[i];
                float dy = p.y - sy[i];
                float dz = p.z - sz[i];
                d2 = dx * dx + dy * dy + dz * dz;
            }
            d2v[j] = d2;
            tm = umin64(tm, ((unsigned long long)__float_as_uint(d2) << 32) | (unsigned)i);
        }
        if (n > NREG) {
#pragma unroll
            for (int j = 8; j < 16; j++) {
                if (256 * j >= n) break;
                int i = tid + 256 * j;
                float d2 = CUDART_INF_F;
                if (i < n) {
                    float dx = p.x - ncoord[(lo + i) * 3 + 0];
                    float dy = p.y - ncoord[(lo + i) * 3 + 1];
                    float dz = p.z - ncoord[(lo + i) * 3 + 2];
                    d2 = dx * dx + dy * dy + dz * dz;
                }
                sdov[i - NREG] = d2;
                tm = umin64(tm, ((unsigned long long)__float_as_uint(d2) << 32) | (unsigned)i);
            }
        }

        // per-warp exact top-KK (registers + shuffles, no barriers)
        for (int r = 0; r < KK; r++) {
            unsigned long long v = tm;
#pragma unroll
            for (int o = 16; o > 0; o >>= 1)
                v = umin64(v, __shfl_down_sync(0xffffffffu, v, o));
            unsigned long long w = __shfl_sync(0xffffffffu, v, 0);
            if (lane == 0) scand[wid * KK + r] = w;
            if (w == tm) {
                // owner lane: invalidate extracted key, recompute local min
#pragma unroll
                for (int j = 0; j < 8; j++) {
                    int i = tid + 256 * j;
                    unsigned long long kj = ((unsigned long long)__float_as_uint(d2v[j]) << 32) | (unsigned)i;
                    if (kj == w) d2v[j] = CUDART_INF_F;
                }
                if (n > NREG) {
#pragma unroll
                    for (int j = 8; j < 16; j++) {
                        if (256 * j >= n) break;
                        int i = tid + 256 * j;
                        unsigned long long kj = ((unsigned long long)__float_as_uint(sdov[i - NREG]) << 32) | (unsigned)i;
                        if (kj == w) sdov[i - NREG] = CUDART_INF_F;
                    }
                }
                tm = ~0ull;
#pragma unroll
                for (int j = 0; j < 8; j++) {
                    int i = tid + 256 * j;
                    tm = umin64(tm, ((unsigned long long)__float_as_uint(d2v[j]) << 32) | (unsigned)i);
                }
                if (n > NREG) {
#pragma unroll
                    for (int j = 8; j < 16; j++) {
                        if (256 * j >= n) break;
                        int i = tid + 256 * j;
                        tm = umin64(tm, ((unsigned long long)__float_as_uint(sdov[i - NREG]) << 32) | (unsigned)i);
                    }
                }
            }
        }
        __syncthreads();

        // warp0: exact top-KK of the 128 candidates (global ascending order)
        if (wid == 0) {
            unsigned long long c0 = scand[lane];
            unsigned long long c1 = scand[lane + 32];
            unsigned long long c2 = scand[lane + 64];
            unsigned long long c3 = scand[lane + 96];
            for (int r = 0; r < KK; r++) {
                unsigned long long v = umin64(umin64(c0, c1), umin64(c2, c3));
#pragma unroll
                for (int o = 16; o > 0; o >>= 1)
                    v = umin64(v, __shfl_down_sync(0xffffffffu, v, o));
                unsigned long long w = __shfl_sync(0xffffffffu, v, 0);
                if (lane == 0) {
                    ssel[r] = (int)(unsigned)w;
                    sd2sel[r] = __uint_as_float((unsigned)(w >> 32));
                }
                if (c0 == w) c0 = ~0ull;
                if (c1 == w) c1 = ~0ull;
                if (c2 == w) c2 = ~0ull;
                if (c3 == w) c3 = ~0ull;
            }
        }
        __syncthreads();

        // rbf basis
        if (tid < KK * NBF) {
            int k = tid >> 3, bb2 = tid & 7;
            float d = sqrtf(fmaxf(sd2sel[k], 1e-12f));
            float e = d - (3.0f / 7.0f) * (float)bb2;
            srbf[tid] = expf(-4.f * e * e);
        }
        __syncthreads();

        // field
        if (tid < DD) {
            float acc = 0.f;
#pragma unroll
            for (int k = 0; k < KK; k++) {
                int gi = lo + ssel[k];
                float coef = 0.f;
#pragma unroll
                for (int bb2 = 0; bb2 < NBF; bb2++)
                    coef = fmaf(srbf[k * NBF + bb2], Wrbf[bb2 * DD + tid], coef);
                acc = fmaf(coef, g_nfext[gi * DD + tid], acc);
            }
            sfield[tid] = acc * g_tf[tid];
        }
        __syncthreads();

        // dtp + per-(t,q) partial (warp0)
        if (tid < CHN) {
            float3 v = qrot(qw0, qx, qy, qz, make_float3(e_vx, e_vy, e_vz));
            float ttv = sfield[tid];
            float3 u = { sfield[CHN + 3 * tid + 0], sfield[CHN + 3 * tid + 1], sfield[CHN + 3 * tid + 2] };
            float3 cr = { v.y * u.z - v.z * u.y, v.z * u.x - v.x * u.z, v.x * u.y - v.y * u.x };
            float lvx = e_al * e_s * u.x + e_bl * ttv * v.x + e_el * cr.x;
            float lvy = e_al * e_s * u.y + e_bl * ttv * v.y + e_el * cr.y;
            float lvz = e_al * e_s * u.z + e_bl * ttv * v.z + e_el * cr.z;
            float avx = e_aa * e_s * u.x + e_ba * ttv * v.x + e_ea * cr.x;
            float avy = e_aa * e_s * u.y + e_ba * ttv * v.y + e_ea * cr.y;
            float avz = e_aa * e_s * u.z + e_ba * ttv * v.z + e_ea * cr.z;
#pragma unroll
            for (int o = 16; o > 0; o >>= 1) {
                lvx += __shfl_down_sync(0xffffffffu, lvx, o);
                lvy += __shfl_down_sync(0xffffffffu, lvy, o);
                lvz += __shfl_down_sync(0xffffffffu, lvz, o);
                avx += __shfl_down_sync(0xffffffffu, avx, o);
                avy += __shfl_down_sync(0xffffffffu, avy, o);
                avz += __shfl_down_sync(0xffffffffu, avz, o);
            }
            if (tid == 0) {
                float3 lv = qrot(qw0, -qx, -qy, -qz, make_float3(lvx, lvy, lvz));
                float3 av = qrot(qw0, -qx, -qy, -qz, make_float3(avx, avy, avz));
                float3 orb = { qc0.y * lv.z - qc0.z * lv.y,
                               qc0.z * lv.x - qc0.x * lv.z,
                               qc0.x * lv.y - qc0.y * lv.x };
                const float inv_s2 = 0.70710678118654752440f;
                float* pp = &g_partial[(t * NQ + qi) * 6];
                pp[0] = e_w * (orb.x + av.x * inv_s2);
                pp[1] = e_w * (orb.y + av.y * inv_s2);
                pp[2] = e_w * (orb.z + av.z * inv_s2);
                pp[3] = e_w * lv.x;
                pp[4] = e_w * lv.y;
                pp[5] = e_w * lv.z;
            }
        }
        __syncthreads();
    }
}

// ---- deterministic final reduction over queries ------------------------------
__global__ void k_reduce(float* __restrict__ out) {
    int t = blockIdx.x, tid = threadIdx.x;
    int lane = tid & 31, wid = tid >> 5;
    float a[6];
    const float* pp = &g_partial[(t * NQ + tid) * 6];
#pragma unroll
    for (int j = 0; j < 6; j++) a[j] = pp[j];
#pragma unroll
    for (int j = 0; j < 6; j++) {
        for (int o = 16; o > 0; o >>= 1)
            a[j] += __shfl_down_sync(0xffffffffu, a[j], o);
    }
    __shared__ float sw[8][6];
    if (lane == 0) {
#pragma unroll
        for (int j = 0; j < 6; j++) sw[wid][j] = a[j];
    }
    __syncthreads();
    if (tid == 0) {
        float r[6] = {0, 0, 0, 0, 0, 0};
        for (int w2 = 0; w2 < 8; w2++)
            for (int j = 0; j < 6; j++) r[j] += sw[w2][j];
        out[t * 3 + 0] = r[0];
        out[t * 3 + 1] = r[1];
        out[t * 3 + 2] = r[2];
        out[NT * 3 + t * 3 + 0] = r[3];
        out[NT * 3 + t * 3 + 1] = r[4];
        out[NT * 3 + t * 3 + 2] = r[5];
    }
}

extern "C" void kernel_launch(void* const* d_in, const int* in_sizes, int n_in,
                              void* d_out, int out_size) {
    const float* T      = (const float*)d_in[0];
    const float* qwgt   = (const float*)d_in[1];
    const float* qfeat  = (const float*)d_in[2];
    const float* qcoord = (const float*)d_in[3];
    const float* nfeat  = (const float*)d_in[4];
    const float* ncoord = (const float*)d_in[5];
    const float* temb   = (const float*)d_in[6];
    const float* Wext   = (const float*)d_in[7];
    const float* Wrbf   = (const float*)d_in[8];
    const float* Wtime  = (const float*)d_in[9];
    const float* wp_lin = (const float*)d_in[10];
    const float* Wv_lin = (const float*)d_in[12];
    const float* wp_ang = (const float*)d_in[13];
    const float* Wv_ang = (const float*)d_in[15];
    const int*   qbatch = (const int*)d_in[16];
    const int*   nbatch = (const int*)d_in[17];
    float* out = (float*)d_out;

    k_pre<<<NNODE / 16 + 1, DD>>>(nfeat, Wext, temb, Wtime, nbatch,
                                  wp_lin, Wv_lin, wp_ang, Wv_ang);
    k_main<<<dim3(NQ, NTG), 256>>>(T, qwgt, qfeat, qcoord, ncoord, Wrbf, qbatch);
    k_reduce<<<NT, NQ>>>(out);
}

// round 8
// speedup vs baseline: 1.4210x; 1.4210x over previous
#include <cuda_runtime.h>
#include <math_constants.h>

#define NT 32
#define NQ 256
#define NNODE 8192
#define DD 128
#define CHN 32
#define KK 16
#define NBF 8
#define BB 4
#define CAP 4096      // hard correctness cap (R6-proven)
#define NCACHE 2048   // coords cached in smem; tail read from global (R7-proven path)
#define NTG 8
#define TPT 4
#define HBINS 2048
#define CANDCAP 128

__device__ float g_nfext[NNODE * DD];
__device__ float g_tf[DD];
__device__ int   g_range[BB + 1];
__device__ float g_coef[6 * CHN];
__device__ float g_partial[NT * NQ * 6];

static __device__ __forceinline__ float3 qrot(float w, float x, float y, float z, float3 v) {
    float uvx = y * v.z - z * v.y;
    float uvy = z * v.x - x * v.z;
    float uvz = x * v.y - y * v.x;
    float wx = y * uvz - z * uvy;
    float wy = z * uvx - x * uvz;
    float wz = x * uvy - y * uvx;
    float3 r;
    r.x = v.x + 2.f * (w * uvx + wx);
    r.y = v.y + 2.f * (w * uvy + wy);
    r.z = v.z + 2.f * (w * uvz + wz);
    return r;
}

// ---- precompute: nf_ext (8 nodes/block, ascending-k chains) + misc -----------
__global__ __launch_bounds__(128) void k_pre(
    const float* __restrict__ nf, const float* __restrict__ Wext,
    const float* __restrict__ te, const float* __restrict__ Wtime,
    const int* __restrict__ nbatch,
    const float* __restrict__ wp_lin, const float* __restrict__ Wv_lin,
    const float* __restrict__ wp_ang, const float* __restrict__ Wv_ang) {
    int tid = threadIdx.x;
    if (blockIdx.x == NNODE / 8) {
        {
            float acc = 0.f;
            for (int k = 0; k < DD; k++) acc = fmaf(te[k], Wtime[k * DD + tid], acc);
            g_tf[tid] = 1.f + acc;
        }
        if (tid <= BB) {
            int lo = 0, hi = NNODE;
            if (tid == BB) lo = NNODE;
            else {
                while (lo < hi) { int m = (lo + hi) >> 1; if (nbatch[m] < tid) lo = m + 1; else hi = m; }
            }
            g_range[tid] = lo;
        }
        if (tid < CHN) {
            for (int g = 0; g < 6; g++) {
                const float* wp = (g < 3) ? wp_lin : wp_ang;
                const float* Wv = (g < 3) ? Wv_lin : Wv_ang;
                int gg = g % 3;
                int wrow = gg * CHN + tid;
                float s = 0.f;
                for (int o = 0; o < CHN; o++) s += Wv[wrow * CHN + o];
                g_coef[g * CHN + tid] = wp[(2 + gg) * CHN + tid] * s * (1.f / (float)CHN);
            }
        }
        return;
    }
    __shared__ float snf[8][DD];
    int b = blockIdx.x;
#pragma unroll
    for (int r = 0; r < 8; r++) snf[r][tid] = nf[(b * 8 + r) * DD + tid];
    __syncthreads();
    float acc[8];
#pragma unroll
    for (int r = 0; r < 8; r++) acc[r] = 0.f;
    for (int k = 0; k < DD; k += 4) {
        float w0 = Wext[(k + 0) * DD + tid];
        float w1 = Wext[(k + 1) * DD + tid];
        float w2 = Wext[(k + 2) * DD + tid];
        float w3 = Wext[(k + 3) * DD + tid];
#pragma unroll
        for (int r = 0; r < 8; r++) {
            float4 s = *(const float4*)&snf[r][k];
            float a = acc[r];
            a = fmaf(s.x, w0, a);    // ascending-k sequential chain (R6-proven order)
            a = fmaf(s.y, w1, a);
            a = fmaf(s.z, w2, a);
            a = fmaf(s.w, w3, a);
            acc[r] = a;
        }
    }
#pragma unroll
    for (int r = 0; r < 8; r++) g_nfext[(b * 8 + r) * DD + tid] = acc[r];
}

// ---- main: block = (query, 4 transforms); histogram radix-select -------------
__global__ __launch_bounds__(256) void k_main(
    const float* __restrict__ T, const float* __restrict__ qwgt,
    const float* __restrict__ qf, const float* __restrict__ qcrd,
    const float* __restrict__ ncoord, const float* __restrict__ Wrbf,
    const int* __restrict__ qbatch) {
    __shared__ float sx[NCACHE], sy[NCACHE], sz[NCACHE];
    __shared__ unsigned hist[HBINS];
    __shared__ unsigned long long cand[CANDCAP];
    __shared__ float srbf[KK * NBF];
    __shared__ float sfield[DD];
    __shared__ int ssel[KK];
    __shared__ float sd2sel[KK];
    __shared__ unsigned swarp[8];
    __shared__ unsigned scnt;
    __shared__ int sB;

    int qi = blockIdx.x, tg = blockIdx.y, tid = threadIdx.x;
    int lane = tid & 31, wid = tid >> 5;

    int b = qbatch[qi];
    int lo = g_range[b];
    int n = g_range[b + 1] - lo;
    if (n > CAP) n = CAP;
    int ncache = n < NCACHE ? n : NCACHE;
    float3 qc0 = { qcrd[qi * 3 + 0], qcrd[qi * 3 + 1], qcrd[qi * 3 + 2] };

    for (int i = tid; i < ncache; i += 256) {
        sx[i] = ncoord[(lo + i) * 3 + 0];
        sy[i] = ncoord[(lo + i) * 3 + 1];
        sz[i] = ncoord[(lo + i) * 3 + 2];
    }

    float e_s = 0.f, e_vx = 0.f, e_vy = 0.f, e_vz = 0.f;
    float e_al = 0.f, e_bl = 0.f, e_el = 0.f, e_aa = 0.f, e_ba = 0.f, e_ea = 0.f, e_w = 0.f;
    if (tid < CHN) {
        e_s  = qf[qi * DD + tid];
        e_vx = qf[qi * DD + CHN + 3 * tid + 0];
        e_vy = qf[qi * DD + CHN + 3 * tid + 1];
        e_vz = qf[qi * DD + CHN + 3 * tid + 2];
        e_al = g_coef[tid];           e_bl = g_coef[CHN + tid];     e_el = g_coef[2 * CHN + tid];
        e_aa = g_coef[3 * CHN + tid]; e_ba = g_coef[4 * CHN + tid]; e_ea = g_coef[5 * CHN + tid];
        e_w  = qwgt[qi];
    }
    __syncthreads();

    for (int tt = 0; tt < TPT; tt++) {
        int t = tg * TPT + tt;
        float qw0 = T[t * 7 + 0], qx = T[t * 7 + 1], qy = T[t * 7 + 2], qz = T[t * 7 + 3];
        float3 p = qrot(qw0, qx, qy, qz, qc0);
        p.x += T[t * 7 + 4]; p.y += T[t * 7 + 5]; p.z += T[t * 7 + 6];

        // phase 0: zero hist / cand / scnt
        for (int h = tid; h < HBINS; h += 256) hist[h] = 0u;
        if (tid < CANDCAP) cand[tid] = ~0ull;
        if (tid == 0) scnt = 0u;
        __syncthreads();

        // phase 1: distances + warp-aggregated histogram (d2 source expr == R6)
        for (int i = tid; i < n; i += 256) {
            float cx, cy, cz;
            if (i < ncache) { cx = sx[i]; cy = sy[i]; cz = sz[i]; }
            else {
                cx = ncoord[(lo + i) * 3 + 0];
                cy = ncoord[(lo + i) * 3 + 1];
                cz = ncoord[(lo + i) * 3 + 2];
            }
            float dx = p.x - cx;
            float dy = p.y - cy;
            float dz = p.z - cz;
            float d2 = dx * dx + dy * dy + dz * dz;
            unsigned bin = __float_as_uint(d2) >> 20;
            unsigned mask = __match_any_sync(__activemask(), bin);
            int leader = __ffs(mask) - 1;
            if (lane == leader) atomicAdd(&hist[bin], (unsigned)__popc(mask));
        }
        __syncthreads();

        // phase 2: block scan over 2048 bins -> threshold bin sB (rank KK)
        unsigned hb[8], mysum = 0;
#pragma unroll
        for (int j = 0; j < 8; j++) { hb[j] = hist[tid * 8 + j]; mysum += hb[j]; }
        unsigned inc = mysum;
#pragma unroll
        for (int o = 1; o < 32; o <<= 1) {
            unsigned v = __shfl_up_sync(0xffffffffu, inc, o);
            if (lane >= o) inc += v;
        }
        if (lane == 31) swarp[wid] = inc;
        __syncthreads();
        unsigned base = 0;
        for (int w = 0; w < wid; w++) base += swarp[w];
        unsigned excl = base + inc - mysum;
        if (excl < KK && excl + mysum >= KK) {
            unsigned cum = excl;
#pragma unroll
            for (int j = 0; j < 8; j++) {
                cum += hb[j];
                if (cum >= KK) { sB = tid * 8 + j; break; }
            }
        }
        __syncthreads();
        unsigned B = (unsigned)sB;

        // phase 3: recompute + collect candidates (bin <= B)
        for (int i = tid; i < n; i += 256) {
            float cx, cy, cz;
            if (i < ncache) { cx = sx[i]; cy = sy[i]; cz = sz[i]; }
            else {
                cx = ncoord[(lo + i) * 3 + 0];
                cy = ncoord[(lo + i) * 3 + 1];
                cz = ncoord[(lo + i) * 3 + 2];
            }
            float dx = p.x - cx;
            float dy = p.y - cy;
            float dz = p.z - cz;
            float d2 = dx * dx + dy * dy + dz * dz;
            unsigned bin = __float_as_uint(d2) >> 20;
            if (bin <= B) {
                unsigned pos = atomicAdd(&scnt, 1u);
                if (pos < CANDCAP)
                    cand[pos] = ((unsigned long long)__float_as_uint(d2) << 32) | (unsigned)i;
            }
        }
        __syncthreads();

        // phase 4: exact rank via LDS-broadcast compares (unique keys)
        if (lane < 16) {
            int ci = wid * 16 + lane;
            unsigned long long my = cand[ci];
            if (my != ~0ull) {
                int r = 0;
                for (int j = 0; j < CANDCAP; j++)
                    r += (cand[j] < my);
                if (r < KK) {
                    ssel[r] = (int)(unsigned)my;
                    sd2sel[r] = __uint_as_float((unsigned)(my >> 32));
                }
            }
        }
        __syncthreads();

        // rbf basis
        if (tid < KK * NBF) {
            int k = tid >> 3, bb2 = tid & 7;
            float d = sqrtf(fmaxf(sd2sel[k], 1e-12f));
            float e = d - (3.0f / 7.0f) * (float)bb2;
            srbf[tid] = expf(-4.f * e * e);
        }
        __syncthreads();

        // field
        if (tid < DD) {
            float acc = 0.f;
#pragma unroll
            for (int k = 0; k < KK; k++) {
                int gi = lo + ssel[k];
                float coef = 0.f;
#pragma unroll
                for (int bb2 = 0; bb2 < NBF; bb2++)
                    coef = fmaf(srbf[k * NBF + bb2], Wrbf[bb2 * DD + tid], coef);
                acc = fmaf(coef, g_nfext[gi * DD + tid], acc);
            }
            sfield[tid] = acc * g_tf[tid];
        }
        __syncthreads();

        // dtp + per-(t,q) partial (warp0)
        if (tid < CHN) {
            float3 v = qrot(qw0, qx, qy, qz, make_float3(e_vx, e_vy, e_vz));
            float ttv = sfield[tid];
            float3 u = { sfield[CHN + 3 * tid + 0], sfield[CHN + 3 * tid + 1], sfield[CHN + 3 * tid + 2] };
            float3 cr = { v.y * u.z - v.z * u.y, v.z * u.x - v.x * u.z, v.x * u.y - v.y * u.x };
            float lvx = e_al * e_s * u.x + e_bl * ttv * v.x + e_el * cr.x;
            float lvy = e_al * e_s * u.y + e_bl * ttv * v.y + e_el * cr.y;
            float lvz = e_al * e_s * u.z + e_bl * ttv * v.z + e_el * cr.z;
            float avx = e_aa * e_s * u.x + e_ba * ttv * v.x + e_ea * cr.x;
            float avy = e_aa * e_s * u.y + e_ba * ttv * v.y + e_ea * cr.y;
            float avz = e_aa * e_s * u.z + e_ba * ttv * v.z + e_ea * cr.z;
#pragma unroll
            for (int o = 16; o > 0; o >>= 1) {
                lvx += __shfl_down_sync(0xffffffffu, lvx, o);
                lvy += __shfl_down_sync(0xffffffffu, lvy, o);
                lvz += __shfl_down_sync(0xffffffffu, lvz, o);
                avx += __shfl_down_sync(0xffffffffu, avx, o);
                avy += __shfl_down_sync(0xffffffffu, avy, o);
                avz += __shfl_down_sync(0xffffffffu, avz, o);
            }
            if (tid == 0) {
                float3 lv = qrot(qw0, -qx, -qy, -qz, make_float3(lvx, lvy, lvz));
                float3 av = qrot(qw0, -qx, -qy, -qz, make_float3(avx, avy, avz));
                float3 orb = { qc0.y * lv.z - qc0.z * lv.y,
                               qc0.z * lv.x - qc0.x * lv.z,
                               qc0.x * lv.y - qc0.y * lv.x };
                const float inv_s2 = 0.70710678118654752440f;
                float* pp = &g_partial[(t * NQ + qi) * 6];
                pp[0] = e_w * (orb.x + av.x * inv_s2);
                pp[1] = e_w * (orb.y + av.y * inv_s2);
                pp[2] = e_w * (orb.z + av.z * inv_s2);
                pp[3] = e_w * lv.x;
                pp[4] = e_w * lv.y;
                pp[5] = e_w * lv.z;
            }
        }
        __syncthreads();
    }
}

// ---- deterministic final reduction over queries ------------------------------
__global__ void k_reduce(float* __restrict__ out) {
    int t = blockIdx.x, tid = threadIdx.x;
    int lane = tid & 31, wid = tid >> 5;
    float a[6];
    const float* pp = &g_partial[(t * NQ + tid) * 6];
#pragma unroll
    for (int j = 0; j < 6; j++) a[j] = pp[j];
#pragma unroll
    for (int j = 0; j < 6; j++) {
        for (int o = 16; o > 0; o >>= 1)
            a[j] += __shfl_down_sync(0xffffffffu, a[j], o);
    }
    __shared__ float sw[8][6];
    if (lane == 0) {
#pragma unroll
        for (int j = 0; j < 6; j++) sw[wid][j] = a[j];
    }
    __syncthreads();
    if (tid == 0) {
        float r[6] = {0, 0, 0, 0, 0, 0};
        for (int w2 = 0; w2 < 8; w2++)
            for (int j = 0; j < 6; j++) r[j] += sw[w2][j];
        out[t * 3 + 0] = r[0];
        out[t * 3 + 1] = r[1];
        out[t * 3 + 2] = r[2];
        out[NT * 3 + t * 3 + 0] = r[3];
        out[NT * 3 + t * 3 + 1] = r[4];
        out[NT * 3 + t * 3 + 2] = r[5];
    }
}

extern "C" void kernel_launch(void* const* d_in, const int* in_sizes, int n_in,
                              void* d_out, int out_size) {
    const float* T      = (const float*)d_in[0];
    const float* qwgt   = (const float*)d_in[1];
    const float* qfeat  = (const float*)d_in[2];
    const float* qcoord = (const float*)d_in[3];
    const float* nfeat  = (const float*)d_in[4];
    const float* ncoord = (const float*)d_in[5];
    const float* temb   = (const float*)d_in[6];
    const float* Wext   = (const float*)d_in[7];
    const float* Wrbf   = (const float*)d_in[8];
    const float* Wtime  = (const float*)d_in[9];
    const float* wp_lin = (const float*)d_in[10];
    const float* Wv_lin = (const float*)d_in[12];
    const float* wp_ang = (const float*)d_in[13];
    const float* Wv_ang = (const float*)d_in[15];
    const int*   qbatch = (const int*)d_in[16];
    const int*   nbatch = (const int*)d_in[17];
    float* out = (float*)d_out;

    k_pre<<<NNODE / 8 + 1, DD>>>(nfeat, Wext, temb, Wtime, nbatch,
                                 wp_lin, Wv_lin, wp_ang, Wv_ang);
    k_main<<<dim3(NQ, NTG), 256>>>(T, qwgt, qfeat, qcoord, ncoord, Wrbf, qbatch);
    k_reduce<<<NT, NQ>>>(out);
}